// round 9
// baseline (speedup 1.0000x reference)
#include <cuda_runtime.h>
#include <cuda_bf16.h>
#include <cstdint>

#define Bsz 128
#define Tsz 1024
#define Dsz 256
#define Hsz 256
#define WPAD 260
#define HPAD 260          // hbuf row pad: 260 % 32 == 4 -> batch rows on disjoint banks
#define PSTR (4 * HPAD)   // phase stride in floats
#define WPG 8             // W chunks register-cached per gate (8 x 16B = 32 floats)

typedef unsigned long long u64;

// ---------------- scratch (__device__ globals; no runtime alloc) ----------
__device__ float g_xproj[(size_t)Bsz * Tsz * 3 * Hsz];          // [B*T,768]
__device__ __nv_bfloat16 g_a_hi[(size_t)Bsz * Tsz * Dsz];       // obs hi
__device__ __nv_bfloat16 g_a_lo[(size_t)Bsz * Tsz * Dsz];       // obs lo
__device__ __nv_bfloat16 g_wt_hi[768 * 256];                    // Wi^T hi [n][k]
__device__ __nv_bfloat16 g_wt_lo[768 * 256];                    // Wi^T lo
__device__ int g_done_mode;

// packed fp32x2 FMA
__device__ __forceinline__ void ffma2(u64& d, u64 a, u64 b) {
    asm("fma.rn.f32x2 %0, %1, %2, %0;" : "+l"(d) : "l"(a), "l"(b));
}
__device__ __forceinline__ float hsum2(u64 v) {
    float2 f = *reinterpret_cast<float2*>(&v);
    return f.x + f.y;
}
__device__ __forceinline__ uint32_t smem_u32(const void* p) {
    uint32_t a;
    asm("{ .reg .u64 t; cvta.to.shared.u64 t, %1; cvt.u32.u64 %0, t; }"
        : "=r"(a) : "l"(p));
    return a;
}
__device__ __forceinline__ void cp16(uint32_t s, const void* g) {
    asm volatile("cp.async.cg.shared.global [%0], [%1], 16;"
                 :: "r"(s), "l"(__cvta_generic_to_global(g)) : "memory");
}
#define LDSM4(r, addr) \
    asm volatile("ldmatrix.sync.aligned.m8n8.x4.shared.b16 {%0,%1,%2,%3}, [%4];" \
                 : "=r"((r)[0]), "=r"((r)[1]), "=r"((r)[2]), "=r"((r)[3]) : "r"(addr))
#define MMA(c, A, b0, b1) \
    asm volatile("mma.sync.aligned.m16n8k16.row.col.f32.bf16.bf16.f32 " \
                 "{%0,%1,%2,%3},{%4,%5,%6,%7},{%8,%9},{%0,%1,%2,%3};" \
                 : "+f"((c)[0]), "+f"((c)[1]), "+f"((c)[2]), "+f"((c)[3]) \
                 : "r"((A)[0]), "r"((A)[1]), "r"((A)[2]), "r"((A)[3]), \
                   "r"(b0), "r"(b1))

// ---------------------------------------------------------------------------
// Kernel 0: detect done dtype
// ---------------------------------------------------------------------------
__global__ void detect_done_kernel(const unsigned int* __restrict__ done_words)
{
    int i = blockIdx.x * blockDim.x + threadIdx.x;   // 32768 words
    if (done_words[i] > 1u) atomicOr(&g_done_mode, 1);
}

// ---------------------------------------------------------------------------
// Kernel A/B: decompose obs / Wi into bf16 hi/lo (unchanged)
// ---------------------------------------------------------------------------
__global__ void decompose_obs(const float* __restrict__ src)
{
    size_t i = (size_t)blockIdx.x * blockDim.x + threadIdx.x;  // float4 index
    float4 v = ((const float4*)src)[i];
    __nv_bfloat16 h0 = __float2bfloat16(v.x);
    __nv_bfloat16 h1 = __float2bfloat16(v.y);
    __nv_bfloat16 h2 = __float2bfloat16(v.z);
    __nv_bfloat16 h3 = __float2bfloat16(v.w);
    __nv_bfloat16 l0 = __float2bfloat16(v.x - __bfloat162float(h0));
    __nv_bfloat16 l1 = __float2bfloat16(v.y - __bfloat162float(h1));
    __nv_bfloat16 l2 = __float2bfloat16(v.z - __bfloat162float(h2));
    __nv_bfloat16 l3 = __float2bfloat16(v.w - __bfloat162float(h3));
    __nv_bfloat162* hp = (__nv_bfloat162*)g_a_hi;
    __nv_bfloat162* lp = (__nv_bfloat162*)g_a_lo;
    hp[2 * i]     = __nv_bfloat162(h0, h1);
    hp[2 * i + 1] = __nv_bfloat162(h2, h3);
    lp[2 * i]     = __nv_bfloat162(l0, l1);
    lp[2 * i + 1] = __nv_bfloat162(l2, l3);
}

__global__ void decompose_wi(const float* __restrict__ Wi)
{
    int idx = blockIdx.x * blockDim.x + threadIdx.x;   // 196608
    int k = idx / 768, n = idx - k * 768;
    float w = Wi[idx];
    __nv_bfloat16 h = __float2bfloat16(w);
    __nv_bfloat16 l = __float2bfloat16(w - __bfloat162float(h));
    g_wt_hi[n * 256 + k] = h;
    g_wt_lo[n * 256 + k] = l;
}

// ---------------------------------------------------------------------------
// Kernel 1: x_proj GEMM via mma.sync bf16 hi/lo (unchanged from R6)
// ---------------------------------------------------------------------------
#define STAGE_B 40960
#define OFF_AHI 0
#define OFF_ALO 10240
#define OFF_BHI 20480
#define OFF_BLO 30720
#define XSMEM   (2 * STAGE_B)

__global__ void __launch_bounds__(256, 2)
xproj_mma_kernel(const float* __restrict__ bi)
{
    extern __shared__ char xsm[];
    const int tid = threadIdx.x, wid = tid >> 5, lane = tid & 31;
    const int warp_m = wid & 3, warp_n = wid >> 2;
    const int bN = blockIdx.x * 128;
    const int bM = blockIdx.y * 128;
    const uint32_t sb = smem_u32(xsm);

    const int grp = lane >> 3, r = lane & 7;
    uint32_t aoff[2], boff[4];
#pragma unroll
    for (int mt = 0; mt < 2; mt++)
        aoff[mt] = (uint32_t)((warp_m * 32 + mt * 16 + (grp & 1) * 8 + r) * 80
                              + (grp >> 1) * 16);
#pragma unroll
    for (int np = 0; np < 4; np++)
        boff[np] = (uint32_t)((warp_n * 64 + np * 16 + (grp >> 1) * 8 + r) * 80
                              + (grp & 1) * 16);

    const int c0row = tid >> 2, c0kc = tid & 3;
    const int c1row = (tid + 256) >> 2, c1kc = (tid + 256) & 3;

    auto load_stage = [&](int ks, int buf) {
        const uint32_t s = sb + buf * STAGE_B;
        const int k0 = ks * 32;
        {
            uint32_t so = c0row * 80 + c0kc * 16;
            size_t ga = (size_t)(bM + c0row) * 256 + k0 + c0kc * 8;
            size_t gb = (size_t)(bN + c0row) * 256 + k0 + c0kc * 8;
            cp16(s + OFF_AHI + so, g_a_hi + ga);
            cp16(s + OFF_ALO + so, g_a_lo + ga);
            cp16(s + OFF_BHI + so, g_wt_hi + gb);
            cp16(s + OFF_BLO + so, g_wt_lo + gb);
        }
        {
            uint32_t so = c1row * 80 + c1kc * 16;
            size_t ga = (size_t)(bM + c1row) * 256 + k0 + c1kc * 8;
            size_t gb = (size_t)(bN + c1row) * 256 + k0 + c1kc * 8;
            cp16(s + OFF_AHI + so, g_a_hi + ga);
            cp16(s + OFF_ALO + so, g_a_lo + ga);
            cp16(s + OFF_BHI + so, g_wt_hi + gb);
            cp16(s + OFF_BLO + so, g_wt_lo + gb);
        }
        asm volatile("cp.async.commit_group;" ::: "memory");
    };

    float acc[2][8][4];
#pragma unroll
    for (int mt = 0; mt < 2; mt++)
#pragma unroll
        for (int nt = 0; nt < 8; nt++)
#pragma unroll
            for (int e = 0; e < 4; e++) acc[mt][nt][e] = 0.f;

    load_stage(0, 0);
    load_stage(1, 1);

#pragma unroll 1
    for (int ks = 0; ks < 8; ks++) {
        if (ks < 7)
            asm volatile("cp.async.wait_group 1;" ::: "memory");
        else
            asm volatile("cp.async.wait_group 0;" ::: "memory");
        __syncthreads();

        const uint32_t s = sb + (ks & 1) * STAGE_B;
#pragma unroll
        for (int h = 0; h < 2; h++) {
            uint32_t a[2][2][4];
#pragma unroll
            for (int mt = 0; mt < 2; mt++) {
                LDSM4(a[0][mt], s + OFF_AHI + aoff[mt] + h * 32);
                LDSM4(a[1][mt], s + OFF_ALO + aoff[mt] + h * 32);
            }
#pragma unroll
            for (int np = 0; np < 4; np++) {
                uint32_t bh[4], bl[4];
                LDSM4(bh, s + OFF_BHI + boff[np] + h * 32);
                LDSM4(bl, s + OFF_BLO + boff[np] + h * 32);
#pragma unroll
                for (int mt = 0; mt < 2; mt++) {
                    MMA(acc[mt][2 * np],     a[0][mt], bh[0], bh[1]);
                    MMA(acc[mt][2 * np + 1], a[0][mt], bh[2], bh[3]);
                    MMA(acc[mt][2 * np],     a[0][mt], bl[0], bl[1]);
                    MMA(acc[mt][2 * np + 1], a[0][mt], bl[2], bl[3]);
                    MMA(acc[mt][2 * np],     a[1][mt], bh[0], bh[1]);
                    MMA(acc[mt][2 * np + 1], a[1][mt], bh[2], bh[3]);
                }
            }
        }
        __syncthreads();
        if (ks + 2 < 8) load_stage(ks + 2, ks & 1);
    }

    const int tq = lane >> 2, tr = lane & 3;
#pragma unroll
    for (int mt = 0; mt < 2; mt++) {
#pragma unroll
        for (int nt = 0; nt < 8; nt++) {
            int row = bM + warp_m * 32 + mt * 16 + tq;
            int col = bN + warp_n * 64 + nt * 8 + tr * 2;
            float2 bb = *(const float2*)(bi + col);
            float2 o0 = make_float2(acc[mt][nt][0] + bb.x, acc[mt][nt][1] + bb.y);
            float2 o1 = make_float2(acc[mt][nt][2] + bb.x, acc[mt][nt][3] + bb.y);
            *(float2*)(g_xproj + (size_t)row * 768 + col)       = o0;
            *(float2*)(g_xproj + (size_t)(row + 8) * 768 + col) = o1;
        }
    }
}

// ---------------------------------------------------------------------------
// Kernel 2: GRU scan R9 — fused layout. 256 threads; thread (c0 = tid>>2,
// g = tid&3) computes full K=256 dots for gates r/z/n of column rank*64+c0,
// batch g, plus the GRU update. No per-step __syncthreads; only the cluster
// barrier. hbuf rows padded to HPAD=260 (batch rows on disjoint banks).
// W register cache: WPG chunks per gate. x/done prefetch under barrier.
// ---------------------------------------------------------------------------
__device__ __forceinline__ float fsigmoid(float x) {
    return __fdividef(1.f, 1.f + __expf(-x));
}
__device__ __forceinline__ float ftanh(float x) {
    return __fdividef(2.f, 1.f + __expf(-2.f * x)) - 1.f;
}

extern __shared__ float smem[];

__global__ void __launch_bounds__(256, 1) __cluster_dims__(4, 1, 1)
scan_kernel(const void* __restrict__ done_raw,
            const float* __restrict__ init_h,
            const float* __restrict__ Wh_rz,
            const float* __restrict__ Wh_n,
            const float* __restrict__ bh_n,
            float* __restrict__ out)
{
    float* W_s   = smem;                       // [192][WPAD]
    float* hbuf  = W_s + 192 * WPAD;           // [2][4][HPAD]
    float* bhn_s = hbuf + 2 * PSTR;            // [64]

    const int tid  = threadIdx.x;
    const int rank = blockIdx.x & 3;
    const int cl   = blockIdx.x >> 2;
    const int b0   = cl * 4;

    const int done_mode = g_done_mode;
    const int* done_i32 = (const int*)done_raw;
    const unsigned char* done_u8 = (const unsigned char*)done_raw;

    // --- load weight slice (transposed into [col][k], pad WPAD) ---
    for (int idx = tid; idx < 192 * 256; idx += 256) {
        int k = idx / 192;
        int c = idx - k * 192;
        float v;
        if (c < 128) {
            int scol = (c < 64) ? (rank * 64 + c) : (256 + rank * 64 + (c - 64));
            v = Wh_rz[(size_t)k * 512 + scol];
        } else {
            v = Wh_n[(size_t)k * 256 + rank * 64 + (c - 128)];
        }
        W_s[c * WPAD + k] = v;
    }
    if (tid < 64) bhn_s[tid] = bh_n[rank * 64 + tid];

    // --- init h phase 0 (padded rows) ---
    for (int idx = tid; idx < 4 * 256; idx += 256) {
        int gg = idx >> 8, kk = idx & 255;
        hbuf[gg * HPAD + kk] = init_h[(size_t)(b0 + gg) * Hsz + kk];
    }
    __syncthreads();

    const int c0 = tid >> 2;     // 0..63
    const int g  = tid & 3;      // 0..3
    const int jg = rank * 64 + c0;
    const float bhn = bhn_s[c0];

    const ulonglong2* w0 = (const ulonglong2*)(W_s + c0 * WPAD);
    const ulonglong2* w1 = (const ulonglong2*)(W_s + (c0 + 64) * WPAD);
    const ulonglong2* w2 = (const ulonglong2*)(W_s + (c0 + 128) * WPAD);

    // register-cache first WPG chunks of each gate's W row
    ulonglong2 w0r[WPG], w1r[WPG], w2r[WPG];
#pragma unroll
    for (int q = 0; q < WPG; q++) { w0r[q] = w0[q]; w1r[q] = w1[q]; w2r[q] = w2[q]; }

    uint32_t hbuf_u32 = smem_u32(hbuf);

    const float* xbase = g_xproj + (size_t)(b0 + g) * Tsz * 768 + jg;
    const size_t done_base = (size_t)(b0 + g) * Tsz;

    float xr = __ldg(xbase);
    float xz = __ldg(xbase + 256);
    float xn = __ldg(xbase + 512);
    int dn = done_mode ? (int)done_u8[done_base] : done_i32[done_base];

    float* ys = out + Bsz * Hsz;
    int p = 0;

    for (int t = 0; t < Tsz; t++) {
        const float* hrow = hbuf + p * PSTR + g * HPAD;
        const ulonglong2* hb = (const ulonglong2*)hrow;

        u64 a0l = 0, a0h = 0, a1l = 0, a1h = 0, a2l = 0, a2h = 0;
#pragma unroll
        for (int i = 0; i < WPG; i++) {
            ulonglong2 h = hb[i];
            ffma2(a0l, w0r[i].x, h.x); ffma2(a0h, w0r[i].y, h.y);
            ffma2(a1l, w1r[i].x, h.x); ffma2(a1h, w1r[i].y, h.y);
            ffma2(a2l, w2r[i].x, h.x); ffma2(a2h, w2r[i].y, h.y);
        }
#pragma unroll 8
        for (int i = WPG; i < 64; i++) {
            ulonglong2 h = hb[i];
            ulonglong2 x0 = w0[i];
            ffma2(a0l, x0.x, h.x); ffma2(a0h, x0.y, h.y);
            ulonglong2 x1 = w1[i];
            ffma2(a1l, x1.x, h.x); ffma2(a1h, x1.y, h.y);
            ulonglong2 x2 = w2[i];
            ffma2(a2l, x2.x, h.x); ffma2(a2h, x2.y, h.y);
        }
        float hr = hsum2(a0l) + hsum2(a0h);
        float hz = hsum2(a1l) + hsum2(a1h);
        float hn = hsum2(a2l) + hsum2(a2h);
        float hcur = hrow[jg];

        if (dn) { hr = 0.f; hz = 0.f; hn = 0.f; hcur = 0.f; }
        float r = fsigmoid(xr + hr);
        float z = fsigmoid(xz + hz);
        float n = ftanh(xn + r * (hn + bhn));
        float hnew = n + z * (hcur - n);

        ys[((size_t)(b0 + g) * Tsz + t) * Hsz + jg] = hnew;
        if (t == Tsz - 1) out[(b0 + g) * Hsz + jg] = hnew;

        // broadcast h_new into all 4 cluster CTAs' next-phase buffer
        uint32_t la = hbuf_u32 + (uint32_t)(((1 - p) * PSTR + g * HPAD + jg) * 4);
#pragma unroll
        for (uint32_t dst = 0; dst < 4; dst++) {
            uint32_t ra;
            asm volatile("mapa.shared::cluster.u32 %0, %1, %2;"
                         : "=r"(ra) : "r"(la), "r"(dst));
            asm volatile("st.shared::cluster.f32 [%0], %1;"
                         :: "r"(ra), "f"(hnew) : "memory");
        }

        asm volatile("barrier.cluster.arrive.aligned;" ::: "memory");
        if (t + 1 < Tsz) {
            const float* xp = xbase + (size_t)(t + 1) * 768;
            xr = __ldg(xp);
            xz = __ldg(xp + 256);
            xn = __ldg(xp + 512);
            size_t di = done_base + t + 1;
            dn = done_mode ? (int)done_u8[di] : done_i32[di];
        }
        asm volatile("barrier.cluster.wait.aligned;" ::: "memory");
        p ^= 1;
    }
}

// ---------------------------------------------------------------------------
// Launch
// ---------------------------------------------------------------------------
static const int SCAN_SMEM_BYTES = (192 * WPAD + 2 * PSTR + 64) * 4;

extern "C" void kernel_launch(void* const* d_in, const int* in_sizes, int n_in,
                              void* d_out, int out_size)
{
    (void)in_sizes; (void)n_in; (void)out_size;
    const float* obs    = (const float*)d_in[0];
    const void*  done   = d_in[1];
    const float* init_h = (const float*)d_in[2];
    const float* Wi     = (const float*)d_in[3];
    const float* bi     = (const float*)d_in[4];
    const float* Wh_rz  = (const float*)d_in[5];
    const float* Wh_n   = (const float*)d_in[6];
    const float* bh_n   = (const float*)d_in[7];
    float* out = (float*)d_out;

    cudaFuncSetAttribute(scan_kernel, cudaFuncAttributeMaxDynamicSharedMemorySize,
                         SCAN_SMEM_BYTES);
    cudaFuncSetAttribute(xproj_mma_kernel, cudaFuncAttributeMaxDynamicSharedMemorySize,
                         XSMEM);

    detect_done_kernel<<<128, 256>>>((const unsigned int*)done);
    decompose_obs<<<32768, 256>>>(obs);
    decompose_wi<<<768, 256>>>(Wi);

    dim3 ggrid(6, 1024);
    xproj_mma_kernel<<<ggrid, 256, XSMEM>>>(bi);

    scan_kernel<<<128, 256, SCAN_SMEM_BYTES>>>(done, init_h, Wh_rz, Wh_n, bh_n, out);
}

// round 10
// speedup vs baseline: 1.2083x; 1.2083x over previous
#include <cuda_runtime.h>
#include <cuda_bf16.h>
#include <cstdint>

#define Bsz 128
#define Tsz 1024
#define Dsz 256
#define Hsz 256

typedef unsigned long long u64;

// ---------------- scratch ----------
__device__ float g_xproj[(size_t)Bsz * Tsz * 3 * Hsz];
__device__ __nv_bfloat16 g_a_hi[(size_t)Bsz * Tsz * Dsz];
__device__ __nv_bfloat16 g_a_lo[(size_t)Bsz * Tsz * Dsz];
__device__ __nv_bfloat16 g_wt_hi[768 * 256];
__device__ __nv_bfloat16 g_wt_lo[768 * 256];
__device__ int g_done_mode;

__device__ __forceinline__ uint32_t smem_u32(const void* p) {
    uint32_t a;
    asm("{ .reg .u64 t; cvta.to.shared.u64 t, %1; cvt.u32.u64 %0, t; }"
        : "=r"(a) : "l"(p));
    return a;
}
__device__ __forceinline__ void cp16(uint32_t s, const void* g) {
    asm volatile("cp.async.cg.shared.global [%0], [%1], 16;"
                 :: "r"(s), "l"(__cvta_generic_to_global(g)) : "memory");
}
#define LDSM4(r, addr) \
    asm volatile("ldmatrix.sync.aligned.m8n8.x4.shared.b16 {%0,%1,%2,%3}, [%4];" \
                 : "=r"((r)[0]), "=r"((r)[1]), "=r"((r)[2]), "=r"((r)[3]) : "r"(addr))
#define MMA(c, A, b0, b1) \
    asm volatile("mma.sync.aligned.m16n8k16.row.col.f32.bf16.bf16.f32 " \
                 "{%0,%1,%2,%3},{%4,%5,%6,%7},{%8,%9},{%0,%1,%2,%3};" \
                 : "+f"((c)[0]), "+f"((c)[1]), "+f"((c)[2]), "+f"((c)[3]) \
                 : "r"((A)[0]), "r"((A)[1]), "r"((A)[2]), "r"((A)[3]), \
                   "r"(b0), "r"(b1))

// ---------------------------------------------------------------------------
__global__ void detect_done_kernel(const unsigned int* __restrict__ done_words)
{
    int i = blockIdx.x * blockDim.x + threadIdx.x;
    if (done_words[i] > 1u) atomicOr(&g_done_mode, 1);
}

__global__ void decompose_obs(const float* __restrict__ src)
{
    size_t i = (size_t)blockIdx.x * blockDim.x + threadIdx.x;
    float4 v = ((const float4*)src)[i];
    __nv_bfloat16 h0 = __float2bfloat16(v.x);
    __nv_bfloat16 h1 = __float2bfloat16(v.y);
    __nv_bfloat16 h2 = __float2bfloat16(v.z);
    __nv_bfloat16 h3 = __float2bfloat16(v.w);
    __nv_bfloat16 l0 = __float2bfloat16(v.x - __bfloat162float(h0));
    __nv_bfloat16 l1 = __float2bfloat16(v.y - __bfloat162float(h1));
    __nv_bfloat16 l2 = __float2bfloat16(v.z - __bfloat162float(h2));
    __nv_bfloat16 l3 = __float2bfloat16(v.w - __bfloat162float(h3));
    __nv_bfloat162* hp = (__nv_bfloat162*)g_a_hi;
    __nv_bfloat162* lp = (__nv_bfloat162*)g_a_lo;
    hp[2 * i]     = __nv_bfloat162(h0, h1);
    hp[2 * i + 1] = __nv_bfloat162(h2, h3);
    lp[2 * i]     = __nv_bfloat162(l0, l1);
    lp[2 * i + 1] = __nv_bfloat162(l2, l3);
}

__global__ void decompose_wi(const float* __restrict__ Wi)
{
    int idx = blockIdx.x * blockDim.x + threadIdx.x;
    int k = idx / 768, n = idx - k * 768;
    float w = Wi[idx];
    __nv_bfloat16 h = __float2bfloat16(w);
    __nv_bfloat16 l = __float2bfloat16(w - __bfloat162float(h));
    g_wt_hi[n * 256 + k] = h;
    g_wt_lo[n * 256 + k] = l;
}

// ---------------------------------------------------------------------------
// Kernel 1: x_proj GEMM (unchanged from R6, known-good)
// ---------------------------------------------------------------------------
#define STAGE_B 40960
#define OFF_AHI 0
#define OFF_ALO 10240
#define OFF_BHI 20480
#define OFF_BLO 30720
#define XSMEM   (2 * STAGE_B)

__global__ void __launch_bounds__(256, 2)
xproj_mma_kernel(const float* __restrict__ bi)
{
    extern __shared__ char xsm[];
    const int tid = threadIdx.x, wid = tid >> 5, lane = tid & 31;
    const int warp_m = wid & 3, warp_n = wid >> 2;
    const int bN = blockIdx.x * 128;
    const int bM = blockIdx.y * 128;
    const uint32_t sb = smem_u32(xsm);

    const int grp = lane >> 3, r = lane & 7;
    uint32_t aoff[2], boff[4];
#pragma unroll
    for (int mt = 0; mt < 2; mt++)
        aoff[mt] = (uint32_t)((warp_m * 32 + mt * 16 + (grp & 1) * 8 + r) * 80
                              + (grp >> 1) * 16);
#pragma unroll
    for (int np = 0; np < 4; np++)
        boff[np] = (uint32_t)((warp_n * 64 + np * 16 + (grp >> 1) * 8 + r) * 80
                              + (grp & 1) * 16);

    const int c0row = tid >> 2, c0kc = tid & 3;
    const int c1row = (tid + 256) >> 2, c1kc = (tid + 256) & 3;

    auto load_stage = [&](int ks, int buf) {
        const uint32_t s = sb + buf * STAGE_B;
        const int k0 = ks * 32;
        {
            uint32_t so = c0row * 80 + c0kc * 16;
            size_t ga = (size_t)(bM + c0row) * 256 + k0 + c0kc * 8;
            size_t gb = (size_t)(bN + c0row) * 256 + k0 + c0kc * 8;
            cp16(s + OFF_AHI + so, g_a_hi + ga);
            cp16(s + OFF_ALO + so, g_a_lo + ga);
            cp16(s + OFF_BHI + so, g_wt_hi + gb);
            cp16(s + OFF_BLO + so, g_wt_lo + gb);
        }
        {
            uint32_t so = c1row * 80 + c1kc * 16;
            size_t ga = (size_t)(bM + c1row) * 256 + k0 + c1kc * 8;
            size_t gb = (size_t)(bN + c1row) * 256 + k0 + c1kc * 8;
            cp16(s + OFF_AHI + so, g_a_hi + ga);
            cp16(s + OFF_ALO + so, g_a_lo + ga);
            cp16(s + OFF_BHI + so, g_wt_hi + gb);
            cp16(s + OFF_BLO + so, g_wt_lo + gb);
        }
        asm volatile("cp.async.commit_group;" ::: "memory");
    };

    float acc[2][8][4];
#pragma unroll
    for (int mt = 0; mt < 2; mt++)
#pragma unroll
        for (int nt = 0; nt < 8; nt++)
#pragma unroll
            for (int e = 0; e < 4; e++) acc[mt][nt][e] = 0.f;

    load_stage(0, 0);
    load_stage(1, 1);

#pragma unroll 1
    for (int ks = 0; ks < 8; ks++) {
        if (ks < 7)
            asm volatile("cp.async.wait_group 1;" ::: "memory");
        else
            asm volatile("cp.async.wait_group 0;" ::: "memory");
        __syncthreads();

        const uint32_t s = sb + (ks & 1) * STAGE_B;
#pragma unroll
        for (int h = 0; h < 2; h++) {
            uint32_t a[2][2][4];
#pragma unroll
            for (int mt = 0; mt < 2; mt++) {
                LDSM4(a[0][mt], s + OFF_AHI + aoff[mt] + h * 32);
                LDSM4(a[1][mt], s + OFF_ALO + aoff[mt] + h * 32);
            }
#pragma unroll
            for (int np = 0; np < 4; np++) {
                uint32_t bh[4], bl[4];
                LDSM4(bh, s + OFF_BHI + boff[np] + h * 32);
                LDSM4(bl, s + OFF_BLO + boff[np] + h * 32);
#pragma unroll
                for (int mt = 0; mt < 2; mt++) {
                    MMA(acc[mt][2 * np],     a[0][mt], bh[0], bh[1]);
                    MMA(acc[mt][2 * np + 1], a[0][mt], bh[2], bh[3]);
                    MMA(acc[mt][2 * np],     a[0][mt], bl[0], bl[1]);
                    MMA(acc[mt][2 * np + 1], a[0][mt], bl[2], bl[3]);
                    MMA(acc[mt][2 * np],     a[1][mt], bh[0], bh[1]);
                    MMA(acc[mt][2 * np + 1], a[1][mt], bh[2], bh[3]);
                }
            }
        }
        __syncthreads();
        if (ks + 2 < 8) load_stage(ks + 2, ks & 1);
    }

    const int tq = lane >> 2, tr = lane & 3;
#pragma unroll
    for (int mt = 0; mt < 2; mt++) {
#pragma unroll
        for (int nt = 0; nt < 8; nt++) {
            int row = bM + warp_m * 32 + mt * 16 + tq;
            int col = bN + warp_n * 64 + nt * 8 + tr * 2;
            float2 bb = *(const float2*)(bi + col);
            float2 o0 = make_float2(acc[mt][nt][0] + bb.x, acc[mt][nt][1] + bb.y);
            float2 o1 = make_float2(acc[mt][nt][2] + bb.x, acc[mt][nt][3] + bb.y);
            *(float2*)(g_xproj + (size_t)row * 768 + col)       = o0;
            *(float2*)(g_xproj + (size_t)(row + 8) * 768 + col) = o1;
        }
    }
}

// ---------------------------------------------------------------------------
// Kernel 2: GRU scan R10 — tensor-core recurrent GEMM.
// 32 clusters x 4 CTAs; CTA rank owns 192 output cols (3 gates x its 64-col
// slice). W in smem as bf16 hi/lo [192n x 256k], pitch 528 (mod128=16 ->
// conflict-free ldmatrix). A-tiles (h, bf16 hi/lo, 8 rows: rows 0-3 = batches)
// double-buffered; ew threads carry fp32 hcur in registers and broadcast
// quantized h to all 4 CTAs each step.
// 768 threads: warps 0..23 = (n-pair 0..11) x (K-half 0..1) mma; ew = tid<256.
// ---------------------------------------------------------------------------
#define BP     528               // row pitch bytes (512 data + 16 pad)
#define SC_WHI 0
#define SC_WLO (192 * BP)        // 101376
#define SC_A   (2 * 192 * BP)    // 202752 ; A[phase][comp][8][BP]
#define SC_APH (2 * 8 * BP)      // 8448
#define SC_ACO (8 * BP)          // 4224
#define SC_ACC (SC_A + 2 * SC_APH)          // 219648 ; accs[2][192][4] f32
#define SC_BHN (SC_ACC + 2 * 192 * 4 * 4)   // 225792 ; 64 f32
#define SC_SMEM (SC_BHN + 256 + 64)

__device__ __forceinline__ float fsigmoid(float x) {
    return __fdividef(1.f, 1.f + __expf(-x));
}
__device__ __forceinline__ float ftanh(float x) {
    return __fdividef(2.f, 1.f + __expf(-2.f * x)) - 1.f;
}

__global__ void __launch_bounds__(768, 1) __cluster_dims__(4, 1, 1)
scan_kernel(const void* __restrict__ done_raw,
            const float* __restrict__ init_h,
            const float* __restrict__ Wh_rz,
            const float* __restrict__ Wh_n,
            const float* __restrict__ bh_n,
            float* __restrict__ out)
{
    extern __shared__ char ssm[];
    const uint32_t sb = smem_u32(ssm);
    float* accs  = (float*)(ssm + SC_ACC);
    float* bhn_s = (float*)(ssm + SC_BHN);

    const int tid  = threadIdx.x;
    const int rank = blockIdx.x & 3;
    const int b0   = (blockIdx.x >> 2) * 4;

    const int done_mode = g_done_mode;
    const int* done_i32 = (const int*)done_raw;
    const unsigned char* done_u8 = (const unsigned char*)done_raw;

    // --- init W slice -> bf16 hi/lo smem [n][k], pitch BP ---
    for (int idx = tid; idx < 192 * 256; idx += 768) {
        int n = idx >> 8, k = idx & 255;
        float w;
        if (n < 64)       w = Wh_rz[(size_t)k * 512 + rank * 64 + n];
        else if (n < 128) w = Wh_rz[(size_t)k * 512 + 256 + rank * 64 + (n - 64)];
        else              w = Wh_n[(size_t)k * 256 + rank * 64 + (n - 128)];
        __nv_bfloat16 hi = __float2bfloat16(w);
        __nv_bfloat16 lo = __float2bfloat16(w - __bfloat162float(hi));
        *(__nv_bfloat16*)(ssm + SC_WHI + n * BP + k * 2) = hi;
        *(__nv_bfloat16*)(ssm + SC_WLO + n * BP + k * 2) = lo;
    }
    if (tid < 64) bhn_s[tid] = bh_n[rank * 64 + tid];

    // --- ew identity + initial A(0)/hcur with done(0) applied ---
    const int g  = (tid >> 6) & 3;
    const int j  = tid & 63;
    const int jg = rank * 64 + j;
    const bool is_ew = (tid < 256);
    const float* xbase = g_xproj + (size_t)(b0 + g) * Tsz * 768 + jg;
    const size_t done_base = (size_t)(b0 + g) * Tsz;

    float hcur = 0.f, xr = 0.f, xz = 0.f, xn = 0.f, bhn = 0.f;
    int dn_next = 0;

    if (is_ew) {
        int d0 = done_mode ? (int)done_u8[done_base] : done_i32[done_base];
        float h0 = d0 ? 0.f : init_h[(size_t)(b0 + g) * Hsz + jg];
        hcur = h0;
        __nv_bfloat16 hb = __float2bfloat16(h0);
        __nv_bfloat16 lb = __float2bfloat16(h0 - __bfloat162float(hb));
        unsigned short hu = __bfloat16_as_ushort(hb);
        unsigned short lu = __bfloat16_as_ushort(lb);
        uint32_t la = sb + SC_A + /*phase0*/ 0 + g * BP + jg * 2;
#pragma unroll
        for (uint32_t dst = 0; dst < 4; dst++) {
            uint32_t ra;
            asm volatile("mapa.shared::cluster.u32 %0, %1, %2;"
                         : "=r"(ra) : "r"(la), "r"(dst));
            asm volatile("st.shared::cluster.u16 [%0], %1;" :: "r"(ra), "h"(hu) : "memory");
            asm volatile("st.shared::cluster.u16 [%0], %1;"
                         :: "r"(ra + SC_ACO), "h"(lu) : "memory");
        }
        xr = __ldg(xbase);
        xz = __ldg(xbase + 256);
        xn = __ldg(xbase + 512);
        dn_next = (Tsz > 1)
            ? (done_mode ? (int)done_u8[done_base + 1] : done_i32[done_base + 1]) : 0;
    }
    __syncthreads();
    asm volatile("barrier.cluster.arrive.aligned;" ::: "memory");
    asm volatile("barrier.cluster.wait.aligned;" ::: "memory");
    if (is_ew) bhn = bhn_s[j];

    // --- mma identity ---
    const int wid = tid >> 5, lane = tid & 31;
    const int nw = wid % 12;        // n-pair (cols nw*16 .. +15)
    const int kh = wid / 12;        // K-half (chunks kh*8 .. +7)
    const int grp = lane >> 3, r = lane & 7;
    // A: rows duplicated for m8-15 (garbage D rows, ignored)
    const uint32_t a_lane = (uint32_t)(r * BP + (grp >> 1) * 16);
    const uint32_t b_hi = sb + SC_WHI
        + (uint32_t)((nw * 16 + (grp >> 1) * 8 + r) * BP + (grp & 1) * 16);
    const uint32_t b_lo = b_hi + (SC_WLO - SC_WHI);
    const int kc0 = kh * 8;
    const int drow = lane >> 2, dcq = lane & 3;   // D frag: lanes 0-15 hold rows 0-3
    const bool dvalid = (lane < 16);

    float* ys = out + Bsz * Hsz;
    int p = 0;

    for (int t = 0; t < Tsz; t++) {
        // ---- mma phase ----
        {
            const uint32_t a_hi = sb + SC_A + p * SC_APH + a_lane;
            const uint32_t a_lo = a_hi + SC_ACO;
            float c0[4] = {0.f, 0.f, 0.f, 0.f};
            float c1[4] = {0.f, 0.f, 0.f, 0.f};
#pragma unroll
            for (int c = 0; c < 8; c++) {
                const uint32_t co = (uint32_t)((kc0 + c) * 32);
                uint32_t ah[4], al[4], bh[4], bl[4];
                LDSM4(ah, a_hi + co);
                LDSM4(al, a_lo + co);
                LDSM4(bh, b_hi + co);
                LDSM4(bl, b_lo + co);
                MMA(c0, ah, bh[0], bh[1]); MMA(c1, ah, bh[2], bh[3]);
                MMA(c0, ah, bl[0], bl[1]); MMA(c1, ah, bl[2], bl[3]);
                MMA(c0, al, bh[0], bh[1]); MMA(c1, al, bh[2], bh[3]);
            }
            if (dvalid) {
                int col0 = nw * 16 + dcq * 2;
                float* ap = accs + (size_t)(kh * 192) * 4;
                ap[(col0)     * 4 + drow] = c0[0];
                ap[(col0 + 1) * 4 + drow] = c0[1];
                ap[(col0 + 8) * 4 + drow] = c1[0];
                ap[(col0 + 9) * 4 + drow] = c1[1];
            }
        }
        __syncthreads();

        // ---- elementwise phase ----
        if (is_ew) {
            float hr = accs[j * 4 + g]           + accs[(192 + j) * 4 + g];
            float hz = accs[(64 + j) * 4 + g]    + accs[(192 + 64 + j) * 4 + g];
            float hn = accs[(128 + j) * 4 + g]   + accs[(192 + 128 + j) * 4 + g];
            float rr = fsigmoid(xr + hr);
            float zz = fsigmoid(xz + hz);
            float nn = ftanh(xn + rr * (hn + bhn));
            float hnew = nn + zz * (hcur - nn);

            ys[((size_t)(b0 + g) * Tsz + t) * Hsz + jg] = hnew;
            if (t == Tsz - 1) out[(b0 + g) * Hsz + jg] = hnew;

            float hw = dn_next ? 0.f : hnew;
            hcur = hw;
            __nv_bfloat16 hb = __float2bfloat16(hw);
            __nv_bfloat16 lb = __float2bfloat16(hw - __bfloat162float(hb));
            unsigned short hu = __bfloat16_as_ushort(hb);
            unsigned short lu = __bfloat16_as_ushort(lb);
            uint32_t la = sb + SC_A + (1 - p) * SC_APH + g * BP + jg * 2;
#pragma unroll
            for (uint32_t dst = 0; dst < 4; dst++) {
                uint32_t ra;
                asm volatile("mapa.shared::cluster.u32 %0, %1, %2;"
                             : "=r"(ra) : "r"(la), "r"(dst));
                asm volatile("st.shared::cluster.u16 [%0], %1;"
                             :: "r"(ra), "h"(hu) : "memory");
                asm volatile("st.shared::cluster.u16 [%0], %1;"
                             :: "r"(ra + SC_ACO), "h"(lu) : "memory");
            }
        }

        asm volatile("barrier.cluster.arrive.aligned;" ::: "memory");
        if (is_ew && t + 1 < Tsz) {
            const float* xp = xbase + (size_t)(t + 1) * 768;
            xr = __ldg(xp);
            xz = __ldg(xp + 256);
            xn = __ldg(xp + 512);
            if (t + 2 < Tsz) {
                size_t di = done_base + t + 2;
                dn_next = done_mode ? (int)done_u8[di] : done_i32[di];
            } else {
                dn_next = 0;
            }
        }
        asm volatile("barrier.cluster.wait.aligned;" ::: "memory");
        p ^= 1;
    }
}

// ---------------------------------------------------------------------------
// Launch
// ---------------------------------------------------------------------------
extern "C" void kernel_launch(void* const* d_in, const int* in_sizes, int n_in,
                              void* d_out, int out_size)
{
    (void)in_sizes; (void)n_in; (void)out_size;
    const float* obs    = (const float*)d_in[0];
    const void*  done   = d_in[1];
    const float* init_h = (const float*)d_in[2];
    const float* Wi     = (const float*)d_in[3];
    const float* bi     = (const float*)d_in[4];
    const float* Wh_rz  = (const float*)d_in[5];
    const float* Wh_n   = (const float*)d_in[6];
    const float* bh_n   = (const float*)d_in[7];
    float* out = (float*)d_out;

    cudaFuncSetAttribute(scan_kernel, cudaFuncAttributeMaxDynamicSharedMemorySize,
                         SC_SMEM);
    cudaFuncSetAttribute(xproj_mma_kernel, cudaFuncAttributeMaxDynamicSharedMemorySize,
                         XSMEM);

    detect_done_kernel<<<128, 256>>>((const unsigned int*)done);
    decompose_obs<<<32768, 256>>>(obs);
    decompose_wi<<<768, 256>>>(Wi);

    dim3 ggrid(6, 1024);
    xproj_mma_kernel<<<ggrid, 256, XSMEM>>>(bi);

    scan_kernel<<<128, 768, SC_SMEM>>>(done, init_h, Wh_rz, Wh_n, bh_n, out);
}

// round 11
// speedup vs baseline: 1.3156x; 1.0887x over previous
#include <cuda_runtime.h>
#include <cuda_bf16.h>
#include <cstdint>

#define Bsz 128
#define Tsz 1024
#define Dsz 256
#define Hsz 256

typedef unsigned long long u64;

// ---------------- scratch ----------
__device__ float g_xproj[(size_t)Bsz * Tsz * 3 * Hsz];
__device__ __nv_bfloat16 g_a_hi[(size_t)Bsz * Tsz * Dsz];
__device__ __nv_bfloat16 g_a_lo[(size_t)Bsz * Tsz * Dsz];
__device__ __nv_bfloat16 g_wt_hi[768 * 256];
__device__ __nv_bfloat16 g_wt_lo[768 * 256];
__device__ int g_done_mode;

__device__ __forceinline__ uint32_t smem_u32(const void* p) {
    uint32_t a;
    asm("{ .reg .u64 t; cvta.to.shared.u64 t, %1; cvt.u32.u64 %0, t; }"
        : "=r"(a) : "l"(p));
    return a;
}
__device__ __forceinline__ void cp16(uint32_t s, const void* g) {
    asm volatile("cp.async.cg.shared.global [%0], [%1], 16;"
                 :: "r"(s), "l"(__cvta_generic_to_global(g)) : "memory");
}
#define LDSM4(r, addr) \
    asm volatile("ldmatrix.sync.aligned.m8n8.x4.shared.b16 {%0,%1,%2,%3}, [%4];" \
                 : "=r"((r)[0]), "=r"((r)[1]), "=r"((r)[2]), "=r"((r)[3]) : "r"(addr))
#define LDSM2(r0, r1, addr) \
    asm volatile("ldmatrix.sync.aligned.m8n8.x2.shared.b16 {%0,%1}, [%2];" \
                 : "=r"(r0), "=r"(r1) : "r"(addr))
#define MMA(c, A, b0, b1) \
    asm volatile("mma.sync.aligned.m16n8k16.row.col.f32.bf16.bf16.f32 " \
                 "{%0,%1,%2,%3},{%4,%5,%6,%7},{%8,%9},{%0,%1,%2,%3};" \
                 : "+f"((c)[0]), "+f"((c)[1]), "+f"((c)[2]), "+f"((c)[3]) \
                 : "r"((A)[0]), "r"((A)[1]), "r"((A)[2]), "r"((A)[3]), \
                   "r"(b0), "r"(b1))
// A-fragment with duplicated m-half (rows 8-15 = rows 0-7, D rows >=4 ignored)
#define MMA_DUP(c, a0, a2, b0, b1) \
    asm volatile("mma.sync.aligned.m16n8k16.row.col.f32.bf16.bf16.f32 " \
                 "{%0,%1,%2,%3},{%4,%5,%6,%7},{%8,%9},{%0,%1,%2,%3};" \
                 : "+f"((c)[0]), "+f"((c)[1]), "+f"((c)[2]), "+f"((c)[3]) \
                 : "r"(a0), "r"(a0), "r"(a2), "r"(a2), "r"(b0), "r"(b1))

// ---------------------------------------------------------------------------
__global__ void detect_done_kernel(const unsigned int* __restrict__ done_words)
{
    int i = blockIdx.x * blockDim.x + threadIdx.x;
    if (done_words[i] > 1u) atomicOr(&g_done_mode, 1);
}

__global__ void decompose_obs(const float* __restrict__ src)
{
    size_t i = (size_t)blockIdx.x * blockDim.x + threadIdx.x;
    float4 v = ((const float4*)src)[i];
    __nv_bfloat16 h0 = __float2bfloat16(v.x);
    __nv_bfloat16 h1 = __float2bfloat16(v.y);
    __nv_bfloat16 h2 = __float2bfloat16(v.z);
    __nv_bfloat16 h3 = __float2bfloat16(v.w);
    __nv_bfloat16 l0 = __float2bfloat16(v.x - __bfloat162float(h0));
    __nv_bfloat16 l1 = __float2bfloat16(v.y - __bfloat162float(h1));
    __nv_bfloat16 l2 = __float2bfloat16(v.z - __bfloat162float(h2));
    __nv_bfloat16 l3 = __float2bfloat16(v.w - __bfloat162float(h3));
    __nv_bfloat162* hp = (__nv_bfloat162*)g_a_hi;
    __nv_bfloat162* lp = (__nv_bfloat162*)g_a_lo;
    hp[2 * i]     = __nv_bfloat162(h0, h1);
    hp[2 * i + 1] = __nv_bfloat162(h2, h3);
    lp[2 * i]     = __nv_bfloat162(l0, l1);
    lp[2 * i + 1] = __nv_bfloat162(l2, l3);
}

__global__ void decompose_wi(const float* __restrict__ Wi)
{
    int idx = blockIdx.x * blockDim.x + threadIdx.x;
    int k = idx / 768, n = idx - k * 768;
    float w = Wi[idx];
    __nv_bfloat16 h = __float2bfloat16(w);
    __nv_bfloat16 l = __float2bfloat16(w - __bfloat162float(h));
    g_wt_hi[n * 256 + k] = h;
    g_wt_lo[n * 256 + k] = l;
}

// ---------------------------------------------------------------------------
// Kernel 1: x_proj GEMM (unchanged from R6, known-good)
// ---------------------------------------------------------------------------
#define STAGE_B 40960
#define OFF_AHI 0
#define OFF_ALO 10240
#define OFF_BHI 20480
#define OFF_BLO 30720
#define XSMEM   (2 * STAGE_B)

__global__ void __launch_bounds__(256, 2)
xproj_mma_kernel(const float* __restrict__ bi)
{
    extern __shared__ char xsm[];
    const int tid = threadIdx.x, wid = tid >> 5, lane = tid & 31;
    const int warp_m = wid & 3, warp_n = wid >> 2;
    const int bN = blockIdx.x * 128;
    const int bM = blockIdx.y * 128;
    const uint32_t sb = smem_u32(xsm);

    const int grp = lane >> 3, r = lane & 7;
    uint32_t aoff[2], boff[4];
#pragma unroll
    for (int mt = 0; mt < 2; mt++)
        aoff[mt] = (uint32_t)((warp_m * 32 + mt * 16 + (grp & 1) * 8 + r) * 80
                              + (grp >> 1) * 16);
#pragma unroll
    for (int np = 0; np < 4; np++)
        boff[np] = (uint32_t)((warp_n * 64 + np * 16 + (grp >> 1) * 8 + r) * 80
                              + (grp & 1) * 16);

    const int c0row = tid >> 2, c0kc = tid & 3;
    const int c1row = (tid + 256) >> 2, c1kc = (tid + 256) & 3;

    auto load_stage = [&](int ks, int buf) {
        const uint32_t s = sb + buf * STAGE_B;
        const int k0 = ks * 32;
        {
            uint32_t so = c0row * 80 + c0kc * 16;
            size_t ga = (size_t)(bM + c0row) * 256 + k0 + c0kc * 8;
            size_t gb = (size_t)(bN + c0row) * 256 + k0 + c0kc * 8;
            cp16(s + OFF_AHI + so, g_a_hi + ga);
            cp16(s + OFF_ALO + so, g_a_lo + ga);
            cp16(s + OFF_BHI + so, g_wt_hi + gb);
            cp16(s + OFF_BLO + so, g_wt_lo + gb);
        }
        {
            uint32_t so = c1row * 80 + c1kc * 16;
            size_t ga = (size_t)(bM + c1row) * 256 + k0 + c1kc * 8;
            size_t gb = (size_t)(bN + c1row) * 256 + k0 + c1kc * 8;
            cp16(s + OFF_AHI + so, g_a_hi + ga);
            cp16(s + OFF_ALO + so, g_a_lo + ga);
            cp16(s + OFF_BHI + so, g_wt_hi + gb);
            cp16(s + OFF_BLO + so, g_wt_lo + gb);
        }
        asm volatile("cp.async.commit_group;" ::: "memory");
    };

    float acc[2][8][4];
#pragma unroll
    for (int mt = 0; mt < 2; mt++)
#pragma unroll
        for (int nt = 0; nt < 8; nt++)
#pragma unroll
            for (int e = 0; e < 4; e++) acc[mt][nt][e] = 0.f;

    load_stage(0, 0);
    load_stage(1, 1);

#pragma unroll 1
    for (int ks = 0; ks < 8; ks++) {
        if (ks < 7)
            asm volatile("cp.async.wait_group 1;" ::: "memory");
        else
            asm volatile("cp.async.wait_group 0;" ::: "memory");
        __syncthreads();

        const uint32_t s = sb + (ks & 1) * STAGE_B;
#pragma unroll
        for (int h = 0; h < 2; h++) {
            uint32_t a[2][2][4];
#pragma unroll
            for (int mt = 0; mt < 2; mt++) {
                LDSM4(a[0][mt], s + OFF_AHI + aoff[mt] + h * 32);
                LDSM4(a[1][mt], s + OFF_ALO + aoff[mt] + h * 32);
            }
#pragma unroll
            for (int np = 0; np < 4; np++) {
                uint32_t bh[4], bl[4];
                LDSM4(bh, s + OFF_BHI + boff[np] + h * 32);
                LDSM4(bl, s + OFF_BLO + boff[np] + h * 32);
#pragma unroll
                for (int mt = 0; mt < 2; mt++) {
                    MMA(acc[mt][2 * np],     a[0][mt], bh[0], bh[1]);
                    MMA(acc[mt][2 * np + 1], a[0][mt], bh[2], bh[3]);
                    MMA(acc[mt][2 * np],     a[0][mt], bl[0], bl[1]);
                    MMA(acc[mt][2 * np + 1], a[0][mt], bl[2], bl[3]);
                    MMA(acc[mt][2 * np],     a[1][mt], bh[0], bh[1]);
                    MMA(acc[mt][2 * np + 1], a[1][mt], bh[2], bh[3]);
                }
            }
        }
        __syncthreads();
        if (ks + 2 < 8) load_stage(ks + 2, ks & 1);
    }

    const int tq = lane >> 2, tr = lane & 3;
#pragma unroll
    for (int mt = 0; mt < 2; mt++) {
#pragma unroll
        for (int nt = 0; nt < 8; nt++) {
            int row = bM + warp_m * 32 + mt * 16 + tq;
            int col = bN + warp_n * 64 + nt * 8 + tr * 2;
            float2 bb = *(const float2*)(bi + col);
            float2 o0 = make_float2(acc[mt][nt][0] + bb.x, acc[mt][nt][1] + bb.y);
            float2 o1 = make_float2(acc[mt][nt][2] + bb.x, acc[mt][nt][3] + bb.y);
            *(float2*)(g_xproj + (size_t)row * 768 + col)       = o0;
            *(float2*)(g_xproj + (size_t)(row + 8) * 768 + col) = o1;
        }
    }
}

// ---------------------------------------------------------------------------
// Kernel 2: GRU scan R11 — W-hi fragments in registers, A via ldmatrix.x2
// with duplicated m-half, B-lo from smem. 512 threads = 16 mma warps:
// warp w: K-half kh=w>>3, tile group wt=w&7 -> n8-tiles {3wt,3wt+1,3wt+2}.
// ew = tid<256 (same protocol as R10).
// ---------------------------------------------------------------------------
#define BP     528
#define SC_WHI 0
#define SC_WLO (192 * BP)
#define SC_A   (2 * 192 * BP)
#define SC_APH (2 * 8 * BP)
#define SC_ACO (8 * BP)
#define SC_ACC (SC_A + 2 * SC_APH)
#define SC_BHN (SC_ACC + 2 * 192 * 4 * 4)
#define SC_SMEM (SC_BHN + 256 + 64)

__device__ __forceinline__ float fsigmoid(float x) {
    return __fdividef(1.f, 1.f + __expf(-x));
}
__device__ __forceinline__ float ftanh(float x) {
    return __fdividef(2.f, 1.f + __expf(-2.f * x)) - 1.f;
}

__global__ void __launch_bounds__(512, 1) __cluster_dims__(4, 1, 1)
scan_kernel(const void* __restrict__ done_raw,
            const float* __restrict__ init_h,
            const float* __restrict__ Wh_rz,
            const float* __restrict__ Wh_n,
            const float* __restrict__ bh_n,
            float* __restrict__ out)
{
    extern __shared__ char ssm[];
    const uint32_t sb = smem_u32(ssm);
    float* accs  = (float*)(ssm + SC_ACC);
    float* bhn_s = (float*)(ssm + SC_BHN);

    const int tid  = threadIdx.x;
    const int rank = blockIdx.x & 3;
    const int b0   = (blockIdx.x >> 2) * 4;

    const int done_mode = g_done_mode;
    const int* done_i32 = (const int*)done_raw;
    const unsigned char* done_u8 = (const unsigned char*)done_raw;

    // --- init W slice -> bf16 hi/lo smem [n][k], pitch BP ---
    for (int idx = tid; idx < 192 * 256; idx += 512) {
        int n = idx >> 8, k = idx & 255;
        float w;
        if (n < 64)       w = Wh_rz[(size_t)k * 512 + rank * 64 + n];
        else if (n < 128) w = Wh_rz[(size_t)k * 512 + 256 + rank * 64 + (n - 64)];
        else              w = Wh_n[(size_t)k * 256 + rank * 64 + (n - 128)];
        __nv_bfloat16 hi = __float2bfloat16(w);
        __nv_bfloat16 lo = __float2bfloat16(w - __bfloat162float(hi));
        *(__nv_bfloat16*)(ssm + SC_WHI + n * BP + k * 2) = hi;
        *(__nv_bfloat16*)(ssm + SC_WLO + n * BP + k * 2) = lo;
    }
    if (tid < 64) bhn_s[tid] = bh_n[rank * 64 + tid];
    __syncthreads();

    // --- mma identity + load B-hi fragments into registers ---
    const int wid = tid >> 5, lane = tid & 31;
    const int kh = wid >> 3;          // K-half: chunks kh*8 .. +7
    const int wt = wid & 7;           // tile group: tiles 3wt..3wt+2
    const int t0 = 3 * wt;
    const int grp = lane >> 3, r = lane & 7;

    uint32_t bhreg[3][8][2];
    {
        const int nrow = lane >> 2, kpair = (lane & 3) * 2;
#pragma unroll
        for (int tt = 0; tt < 3; tt++) {
            const uint32_t base = (uint32_t)(((t0 + tt) * 8 + nrow) * BP);
#pragma unroll
            for (int c = 0; c < 8; c++) {
                const uint32_t koff = (uint32_t)((kh * 8 + c) * 32 + kpair * 2);
                bhreg[tt][c][0] = *(const uint32_t*)(ssm + SC_WHI + base + koff);
                bhreg[tt][c][1] = *(const uint32_t*)(ssm + SC_WHI + base + koff + 16);
            }
        }
    }

    // A LDSM2 lane offset (lanes 0-15 used): matrix0 = rows m0-7 k0-7,
    // matrix1 = rows m0-7 k8-15
    const uint32_t a_lane = (uint32_t)((lane & 7) * BP + (((lane >> 3) & 1) ? 16 : 0));
    // B-lo LDSM4 (tiles t0,t0+1): rows t0*8 + (grp>>1)*8 + r, byte (grp&1)*16
    const uint32_t bl4 = sb + SC_WLO
        + (uint32_t)((t0 * 8 + (grp >> 1) * 8 + r) * BP + (grp & 1) * 16);
    // B-lo LDSM2 (tile t0+2): rows (t0+2)*8 + r, byte (lane>=8)*16
    const uint32_t bl2 = sb + SC_WLO
        + (uint32_t)(((t0 + 2) * 8 + (lane & 7)) * BP + (((lane >> 3) & 1) ? 16 : 0));

    const int kc0 = kh * 8;
    const int drow = lane >> 2, dcq = lane & 3;
    const bool dvalid = (lane < 16);

    // --- ew identity + initial A(0)/hcur ---
    const int g  = (tid >> 6) & 3;
    const int j  = tid & 63;
    const int jg = rank * 64 + j;
    const bool is_ew = (tid < 256);
    const float* xbase = g_xproj + (size_t)(b0 + g) * Tsz * 768 + jg;
    const size_t done_base = (size_t)(b0 + g) * Tsz;

    float hcur = 0.f, xr = 0.f, xz = 0.f, xn = 0.f, bhn = 0.f;
    int dn_next = 0;

    if (is_ew) {
        int d0 = done_mode ? (int)done_u8[done_base] : done_i32[done_base];
        float h0 = d0 ? 0.f : init_h[(size_t)(b0 + g) * Hsz + jg];
        hcur = h0;
        __nv_bfloat16 hb = __float2bfloat16(h0);
        __nv_bfloat16 lb = __float2bfloat16(h0 - __bfloat162float(hb));
        unsigned short hu = __bfloat16_as_ushort(hb);
        unsigned short lu = __bfloat16_as_ushort(lb);
        uint32_t la = sb + SC_A + g * BP + jg * 2;
#pragma unroll
        for (uint32_t dst = 0; dst < 4; dst++) {
            uint32_t ra;
            asm volatile("mapa.shared::cluster.u32 %0, %1, %2;"
                         : "=r"(ra) : "r"(la), "r"(dst));
            asm volatile("st.shared::cluster.u16 [%0], %1;" :: "r"(ra), "h"(hu) : "memory");
            asm volatile("st.shared::cluster.u16 [%0], %1;"
                         :: "r"(ra + SC_ACO), "h"(lu) : "memory");
        }
        xr = __ldg(xbase);
        xz = __ldg(xbase + 256);
        xn = __ldg(xbase + 512);
        dn_next = done_mode ? (int)done_u8[done_base + 1] : done_i32[done_base + 1];
        bhn = bhn_s[j];
    }
    __syncthreads();
    asm volatile("barrier.cluster.arrive.aligned;" ::: "memory");
    asm volatile("barrier.cluster.wait.aligned;" ::: "memory");

    float* ys = out + Bsz * Hsz;
    int p = 0;

    for (int t = 0; t < Tsz; t++) {
        // ---- mma phase ----
        {
            const uint32_t a_hi = sb + SC_A + p * SC_APH + a_lane;
            const uint32_t a_lo = a_hi + SC_ACO;
            float c0[4] = {0.f, 0.f, 0.f, 0.f};
            float c1[4] = {0.f, 0.f, 0.f, 0.f};
            float c2[4] = {0.f, 0.f, 0.f, 0.f};
#pragma unroll
            for (int c = 0; c < 8; c++) {
                const uint32_t co = (uint32_t)((kc0 + c) * 32);
                uint32_t ah0, ah2, al0, al2;
                LDSM2(ah0, ah2, a_hi + co);
                LDSM2(al0, al2, a_lo + co);
                uint32_t bl[4], bl20, bl21;
                LDSM4(bl, bl4 + co);
                LDSM2(bl20, bl21, bl2 + co);
                // tile 0
                MMA_DUP(c0, ah0, ah2, bhreg[0][c][0], bhreg[0][c][1]);
                MMA_DUP(c0, al0, al2, bhreg[0][c][0], bhreg[0][c][1]);
                MMA_DUP(c0, ah0, ah2, bl[0], bl[1]);
                // tile 1
                MMA_DUP(c1, ah0, ah2, bhreg[1][c][0], bhreg[1][c][1]);
                MMA_DUP(c1, al0, al2, bhreg[1][c][0], bhreg[1][c][1]);
                MMA_DUP(c1, ah0, ah2, bl[2], bl[3]);
                // tile 2
                MMA_DUP(c2, ah0, ah2, bhreg[2][c][0], bhreg[2][c][1]);
                MMA_DUP(c2, al0, al2, bhreg[2][c][0], bhreg[2][c][1]);
                MMA_DUP(c2, ah0, ah2, bl20, bl21);
            }
            if (dvalid) {
                float* ap = accs + (size_t)(kh * 192) * 4;
                int cA = t0 * 8 + dcq * 2;
                ap[(cA)     * 4 + drow] = c0[0];
                ap[(cA + 1) * 4 + drow] = c0[1];
                ap[(cA + 8) * 4 + drow] = c1[0];
                ap[(cA + 9) * 4 + drow] = c1[1];
                ap[(cA + 16) * 4 + drow] = c2[0];
                ap[(cA + 17) * 4 + drow] = c2[1];
            }
        }
        __syncthreads();

        // ---- elementwise phase ----
        if (is_ew) {
            float hr = accs[j * 4 + g]           + accs[(192 + j) * 4 + g];
            float hz = accs[(64 + j) * 4 + g]    + accs[(192 + 64 + j) * 4 + g];
            float hn = accs[(128 + j) * 4 + g]   + accs[(192 + 128 + j) * 4 + g];
            float rr = fsigmoid(xr + hr);
            float zz = fsigmoid(xz + hz);
            float nn = ftanh(xn + rr * (hn + bhn));
            float hnew = nn + zz * (hcur - nn);

            ys[((size_t)(b0 + g) * Tsz + t) * Hsz + jg] = hnew;
            if (t == Tsz - 1) out[(b0 + g) * Hsz + jg] = hnew;

            float hw = dn_next ? 0.f : hnew;
            hcur = hw;
            __nv_bfloat16 hb = __float2bfloat16(hw);
            __nv_bfloat16 lb = __float2bfloat16(hw - __bfloat162float(hb));
            unsigned short hu = __bfloat16_as_ushort(hb);
            unsigned short lu = __bfloat16_as_ushort(lb);
            uint32_t la = sb + SC_A + (1 - p) * SC_APH + g * BP + jg * 2;
#pragma unroll
            for (uint32_t dst = 0; dst < 4; dst++) {
                uint32_t ra;
                asm volatile("mapa.shared::cluster.u32 %0, %1, %2;"
                             : "=r"(ra) : "r"(la), "r"(dst));
                asm volatile("st.shared::cluster.u16 [%0], %1;"
                             :: "r"(ra), "h"(hu) : "memory");
                asm volatile("st.shared::cluster.u16 [%0], %1;"
                             :: "r"(ra + SC_ACO), "h"(lu) : "memory");
            }
        }

        asm volatile("barrier.cluster.arrive.aligned;" ::: "memory");
        if (is_ew && t + 1 < Tsz) {
            const float* xp = xbase + (size_t)(t + 1) * 768;
            xr = __ldg(xp);
            xz = __ldg(xp + 256);
            xn = __ldg(xp + 512);
            if (t + 2 < Tsz) {
                size_t di = done_base + t + 2;
                dn_next = done_mode ? (int)done_u8[di] : done_i32[di];
            } else {
                dn_next = 0;
            }
        }
        asm volatile("barrier.cluster.wait.aligned;" ::: "memory");
        p ^= 1;
    }
}

// ---------------------------------------------------------------------------
// Launch
// ---------------------------------------------------------------------------
extern "C" void kernel_launch(void* const* d_in, const int* in_sizes, int n_in,
                              void* d_out, int out_size)
{
    (void)in_sizes; (void)n_in; (void)out_size;
    const float* obs    = (const float*)d_in[0];
    const void*  done   = d_in[1];
    const float* init_h = (const float*)d_in[2];
    const float* Wi     = (const float*)d_in[3];
    const float* bi     = (const float*)d_in[4];
    const float* Wh_rz  = (const float*)d_in[5];
    const float* Wh_n   = (const float*)d_in[6];
    const float* bh_n   = (const float*)d_in[7];
    float* out = (float*)d_out;

    cudaFuncSetAttribute(scan_kernel, cudaFuncAttributeMaxDynamicSharedMemorySize,
                         SC_SMEM);
    cudaFuncSetAttribute(xproj_mma_kernel, cudaFuncAttributeMaxDynamicSharedMemorySize,
                         XSMEM);

    detect_done_kernel<<<128, 256>>>((const unsigned int*)done);
    decompose_obs<<<32768, 256>>>(obs);
    decompose_wi<<<768, 256>>>(Wi);

    dim3 ggrid(6, 1024);
    xproj_mma_kernel<<<ggrid, 256, XSMEM>>>(bi);

    scan_kernel<<<128, 512, SC_SMEM>>>(done, init_h, Wh_rz, Wh_n, bh_n, out);
}